// round 9
// baseline (speedup 1.0000x reference)
#include <cuda_runtime.h>
#include <cuda_fp16.h>
#include <cstdint>

// LoRAConv1D: out = x @ W + b + 4.0 * (x @ A) @ B
//   x:[8192,1600]f32  W:[1600,4800]f32  b:[4800]  A:[1600,8]  B:[8,4800]
//
// Single-product fp16 tensor path (sm_103 non-'a' target):
//  1) W' = W + 4*A@B rounded fp16, transposed [N,K]
//  2) x rounded fp16 [M,K]
//  3) out = fp16(x)*fp16(W') + b, fp32 accum via mma.sync m16n8k16
//     (calibrated rel err 2.93e-4 < 1e-3)
//  GEMM: BM=256 BN=96 BK=64 -> grid 50x32 = 1600 CTAs = 10.81 waves on
//  148 SMs (tail cost 1.7% vs 9.5% at BN=128). 512 threads, warp grid 8x2,
//  warp tile 32x48, 4-stage cp.async (44KB/stage), SW128 swizzle,
//  B-fragment software pipelining incl. cross-iteration prefetch.

#define M_TOT 8192
#define N_TOT 4800
#define K_TOT 1600
#define RANK  8

#define BM 256
#define BN 96
#define BK 64
#define KITERS (K_TOT / BK)        // 25

// stage layout (bytes): A[256*128] B[96*128]
#define A_OFF 0
#define B_OFF 32768
#define STAGE_BYTES 45056
#define SMEM_TOTAL (4 * STAGE_BYTES)   // 180224

// ---------------- device scratch (static, alloc-free) ----------------------
__device__ __half g_x[(size_t)M_TOT * K_TOT];    // fp16 x
__device__ __half g_w[(size_t)N_TOT * K_TOT];    // [N,K] fp16 W'

// ---------------- helpers ---------------------------------------------------
__device__ __forceinline__ uint32_t smem_u32(const void* p) {
    uint32_t a;
    asm("{ .reg .u64 t; cvta.to.shared.u64 t, %1; cvt.u32.u64 %0, t; }"
        : "=r"(a) : "l"(p));
    return a;
}
// 128B-pitch SW128 swizzle: 16B chunk ch of row -> ch ^ (row & 7).
__device__ __forceinline__ uint32_t swz128(int row, int ch) {
    return (uint32_t)(row * 128 + 16 * (ch ^ (row & 7)));
}
__device__ __forceinline__ void cp16(uint32_t dst, const void* src) {
    asm volatile("cp.async.cg.shared.global [%0], [%1], 16;"
                 :: "r"(dst), "l"(src));
}
#define CP_COMMIT() asm volatile("cp.async.commit_group;")
#define CP_WAIT2()  asm volatile("cp.async.wait_group 2;")

__device__ __forceinline__ void ldm_x4(uint32_t* r, uint32_t addr) {
    asm volatile("ldmatrix.sync.aligned.m8n8.x4.shared.b16 {%0,%1,%2,%3}, [%4];"
                 : "=r"(r[0]), "=r"(r[1]), "=r"(r[2]), "=r"(r[3]) : "r"(addr));
}
__device__ __forceinline__ void mma_f16(float* d, const uint32_t* a,
                                        const uint32_t* b) {
    asm volatile(
        "mma.sync.aligned.m16n8k16.row.col.f32.f16.f16.f32 "
        "{%0,%1,%2,%3}, {%4,%5,%6,%7}, {%8,%9}, {%0,%1,%2,%3};"
        : "+f"(d[0]), "+f"(d[1]), "+f"(d[2]), "+f"(d[3])
        : "r"(a[0]), "r"(a[1]), "r"(a[2]), "r"(a[3]), "r"(b[0]), "r"(b[1]));
}

// ---------------- kernel 1: x -> fp16 ---------------------------------------
__global__ void convert_x_kernel(const float* __restrict__ x) {
    size_t base = ((size_t)blockIdx.x * blockDim.x + threadIdx.x) * 8;
    if (base >= (size_t)M_TOT * K_TOT) return;
    float v[8];
    *(float4*)(v)     = *(const float4*)(x + base);
    *(float4*)(v + 4) = *(const float4*)(x + base + 4);
    uint4 ph;
    __half* hp = (__half*)&ph;
#pragma unroll
    for (int j = 0; j < 8; j++) hp[j] = __float2half_rn(v[j]);
    *(uint4*)((char*)g_x + base * 2) = ph;
}

// ---------------- kernel 2: W' = W + 4*A@B -> fp16, transposed [N,K] --------
__global__ void fuse_w_kernel(const float* __restrict__ W,
                              const float* __restrict__ A,
                              const float* __restrict__ Bl) {
    __shared__ __half sh[32][33];
    const int n0 = blockIdx.x * 32, k0 = blockIdx.y * 32;
    const int tx = threadIdx.x & 31, ty = threadIdx.x >> 5;   // 32 x 8
#pragma unroll
    for (int rr = 0; rr < 4; rr++) {
        int k = k0 + ty + rr * 8, n = n0 + tx;
        float acc = W[(size_t)k * N_TOT + n];
#pragma unroll
        for (int r = 0; r < RANK; r++)
            acc += 4.0f * A[k * RANK + r] * Bl[r * N_TOT + n];
        sh[ty + rr * 8][tx] = __float2half_rn(acc);
    }
    __syncthreads();
#pragma unroll
    for (int rr = 0; rr < 4; rr++) {
        int n = n0 + ty + rr * 8, k = k0 + tx;
        g_w[(size_t)n * K_TOT + k] = sh[tx][ty + rr * 8];
    }
}

// ---------------- kernel 3: fp16 mma.sync GEMM ------------------------------
// 16 warps: wm = wid&7 (32-row slab), wn = wid>>3 (48-col slab).
// Warp tile 32x48: mt=2 (m16), nt=6 (n8) -> acc[2][6][4] = 48 regs.
__global__ __launch_bounds__(512, 1)
void gemm_kernel(const float* __restrict__ bias, float* __restrict__ out) {
    extern __shared__ char smem[];
    const uint32_t sb = smem_u32(smem);
    const int tid = threadIdx.x, lane = tid & 31, wid = tid >> 5;
    const int wm = wid & 7;
    const int wn = wid >> 3;
    const int m0 = blockIdx.y * BM;
    const int n0 = blockIdx.x * BN;
    const uint32_t l7 = lane & 7;

    // ---- fragment base addresses (row*128); chunk XOR applied per kk ----
    uint32_t aBase[2];
#pragma unroll
    for (int mt = 0; mt < 2; mt++)
        aBase[mt] = A_OFF + (uint32_t)(wm * 32 + mt * 16 + (lane & 15)) * 128;
    uint32_t bBase[3];
#pragma unroll
    for (int p = 0; p < 3; p++)
        bBase[p] = B_OFF +
            (uint32_t)(wn * 48 + (2 * p + ((lane >> 4) & 1)) * 8 + l7) * 128;
    const uint32_t aSel = lane >> 4;          // A k-half from bit 4
    const uint32_t bSel = (lane >> 3) & 1;    // B k-half from bit 3

    float acc[2][6][4];
#pragma unroll
    for (int i = 0; i < 2; i++)
#pragma unroll
        for (int j = 0; j < 6; j++)
#pragma unroll
            for (int k = 0; k < 4; k++) acc[i][j][k] = 0.0f;

    // ---- stage loader: A 2048 + B 768 chunks of 16B over 512 threads ------
    auto load_stage = [&](int s, int k0) {
        const uint32_t st = sb + s * STAGE_BYTES;
#pragma unroll
        for (int i = 0; i < 4; i++) {
            int idx = tid + i * 512;
            int row = idx >> 3, ch = idx & 7;
            cp16(st + A_OFF + swz128(row, ch),
                 g_x + (size_t)(m0 + row) * K_TOT + k0 + ch * 8);
        }
        {
            int row = tid >> 3, ch = tid & 7;
            cp16(st + B_OFF + swz128(row, ch),
                 g_w + (size_t)(n0 + row) * K_TOT + k0 + ch * 8);
            if (tid < 256) {
                int idx = tid + 512;
                row = idx >> 3; ch = idx & 7;
                cp16(st + B_OFF + swz128(row, ch),
                     g_w + (size_t)(n0 + row) * K_TOT + k0 + ch * 8);
            }
        }
    };

    // xor chunk offsets for fragment loads at k-step kk
    auto xA = [&](int kk) { return 16u * (((uint32_t)(kk * 2) + aSel) ^ l7); };
    auto xB = [&](int kk) { return 16u * (((uint32_t)(kk * 2) + bSel) ^ l7); };

    // ---- prologue: fill 3 stages ----
    load_stage(0, 0);       CP_COMMIT();
    load_stage(1, BK);      CP_COMMIT();
    load_stage(2, 2 * BK);  CP_COMMIT();
    CP_WAIT2();             // stage 0 complete
    __syncthreads();

    // B fragments double buffer; preload iter0 kk0
    uint32_t bf[2][3][4];
    {
        const uint32_t st0 = sb + 0 * STAGE_BYTES;
#pragma unroll
        for (int p = 0; p < 3; p++) ldm_x4(bf[0][p], st0 + bBase[p] + xB(0));
    }

    // ---- mainloop ----
    for (int t = 0; t < KITERS; t++) {
        const uint32_t st = sb + (t & 3) * STAGE_BYTES;

        // issue load of stage t+3 (overwrites slot (t-1)&3, protected by the
        // barrier at the end of the previous iteration)
        if (t + 3 < KITERS) load_stage((t + 3) & 3, (t + 3) * BK);
        CP_COMMIT();

#pragma unroll
        for (int kk = 0; kk < 4; kk++) {
            const int cb = kk & 1, nb = cb ^ 1;
            uint32_t a[2][4];
#pragma unroll
            for (int mt = 0; mt < 2; mt++)
                ldm_x4(a[mt], st + aBase[mt] + xA(kk));
            if (kk < 3) {                     // prefetch next kk's B frags
#pragma unroll
                for (int p = 0; p < 3; p++)
                    ldm_x4(bf[nb][p], st + bBase[p] + xB(kk + 1));
            }
#pragma unroll
            for (int mt = 0; mt < 2; mt++)
#pragma unroll
                for (int p = 0; p < 3; p++) {
                    mma_f16(acc[mt][2 * p],     a[mt], &bf[cb][p][0]);
                    mma_f16(acc[mt][2 * p + 1], a[mt], &bf[cb][p][2]);
                }
        }

        CP_WAIT2();                           // stage t+1 landed
        if (t + 1 < KITERS) {
            // cross-iteration prefetch: kk0 B frags of stage t+1.
            // Safe before the barrier: reads stage (t+1)&3, while the next
            // iteration's writes target stage (t+3)&3 != (t+1)&3.
            const uint32_t stn = sb + ((t + 1) & 3) * STAGE_BYTES;
#pragma unroll
            for (int p = 0; p < 3; p++)
                ldm_x4(bf[0][p], stn + bBase[p] + xB(0));
        }
        __syncthreads();                      // all reads of stage t done
    }

    // ---- epilogue: add bias, float2 stores (N=4800 divides, no guard) ----
    const int r0 = lane >> 2, c0 = (lane & 3) * 2;
#pragma unroll
    for (int mt = 0; mt < 2; mt++)
#pragma unroll
        for (int nt = 0; nt < 6; nt++) {
            const int col = n0 + wn * 48 + nt * 8 + c0;
            const float bx = bias[col], by = bias[col + 1];
#pragma unroll
            for (int h = 0; h < 2; h++) {
                const int row = m0 + wm * 32 + mt * 16 + r0 + h * 8;
                float2 v;
                v.x = acc[mt][nt][h * 2 + 0] + bx;
                v.y = acc[mt][nt][h * 2 + 1] + by;
                *(float2*)(out + (size_t)row * N_TOT + col) = v;
            }
        }
}

// ---------------------------------------------------------------------------
extern "C" void kernel_launch(void* const* d_in, const int* in_sizes, int n_in,
                              void* d_out, int out_size) {
    const float* x  = (const float*)d_in[0];
    const float* W  = (const float*)d_in[1];
    const float* b  = (const float*)d_in[2];
    const float* lA = (const float*)d_in[3];
    const float* lB = (const float*)d_in[4];
    float* out = (float*)d_out;
    (void)in_sizes; (void)n_in; (void)out_size;

    {   // x -> fp16
        size_t total = (size_t)M_TOT * K_TOT / 8;
        convert_x_kernel<<<(unsigned)((total + 255) / 256), 256>>>(x);
    }
    {   // fuse LoRA + round + transpose W
        dim3 grid(N_TOT / 32, K_TOT / 32);   // (150, 50)
        fuse_w_kernel<<<grid, 256>>>(W, lA, lB);
    }
    {   // fp16 tensor-core GEMM
        cudaFuncSetAttribute(gemm_kernel,
                             cudaFuncAttributeMaxDynamicSharedMemorySize,
                             SMEM_TOTAL);
        dim3 grid(N_TOT / BN, M_TOT / BM);   // (50, 32) = 1600 CTAs
        gemm_kernel<<<grid, 512, SMEM_TOTAL>>>(b, out);
    }
}

// round 10
// speedup vs baseline: 1.7555x; 1.7555x over previous
#include <cuda_runtime.h>
#include <cuda_fp16.h>
#include <cstdint>

// LoRAConv1D: out = x @ W + b + 4.0 * (x @ A) @ B
//   x:[8192,1600]f32  W:[1600,4800]f32  b:[4800]  A:[1600,8]  B:[8,4800]
//
// Single-product fp16 tensor path (sm_103 non-'a' target):
//  1) W' = W + 4*A@B rounded fp16, transposed [N,K], N padded 4800->4864
//  2) x rounded fp16 [M,K]
//  3) out = fp16(x)*fp16(W') + b, fp32 accum via mma.sync m16n8k16
//     (calibrated rel err 2.93e-4 < 1e-3)
//  GEMM: BM=128 BN=128 BK=64, 256 threads (8 warps, 2x4), warp tile 64x32
//  (same per-warp shape as the 346us R8 kernel), 3-stage cp.async
//  (32KB/stage) -> 2 CTAs/SM (16 warps/SM) for cross-CTA latency hiding.

#define M_TOT 8192
#define N_TOT 4800
#define N_PAD 4864
#define K_TOT 1600
#define RANK  8

#define BM 128
#define BN 128
#define BK 64
#define KITERS (K_TOT / BK)        // 25

// stage layout (bytes): A[128*128] B[128*128]
#define A_OFF 0
#define B_OFF 16384
#define STAGE_BYTES 32768
#define SMEM_TOTAL (3 * STAGE_BYTES)   // 98304 per CTA -> 2 CTAs/SM

// ---------------- device scratch (static, alloc-free) ----------------------
__device__ __half g_x[(size_t)M_TOT * K_TOT];    // fp16 x
__device__ __half g_w[(size_t)N_PAD * K_TOT];    // [N_PAD,K] fp16 W' (pad=0)

// ---------------- helpers ---------------------------------------------------
__device__ __forceinline__ uint32_t smem_u32(const void* p) {
    uint32_t a;
    asm("{ .reg .u64 t; cvta.to.shared.u64 t, %1; cvt.u32.u64 %0, t; }"
        : "=r"(a) : "l"(p));
    return a;
}
// 128B-pitch SW128 swizzle: 16B chunk ch of row -> ch ^ (row & 7).
__device__ __forceinline__ uint32_t swz128(int row, int ch) {
    return (uint32_t)(row * 128 + 16 * (ch ^ (row & 7)));
}
__device__ __forceinline__ void cp16(uint32_t dst, const void* src) {
    asm volatile("cp.async.cg.shared.global [%0], [%1], 16;"
                 :: "r"(dst), "l"(src));
}
#define CP_COMMIT() asm volatile("cp.async.commit_group;")
#define CP_WAIT1()  asm volatile("cp.async.wait_group 1;")

__device__ __forceinline__ void ldm_x4(uint32_t* r, uint32_t addr) {
    asm volatile("ldmatrix.sync.aligned.m8n8.x4.shared.b16 {%0,%1,%2,%3}, [%4];"
                 : "=r"(r[0]), "=r"(r[1]), "=r"(r[2]), "=r"(r[3]) : "r"(addr));
}
__device__ __forceinline__ void mma_f16(float* d, const uint32_t* a,
                                        const uint32_t* b) {
    asm volatile(
        "mma.sync.aligned.m16n8k16.row.col.f32.f16.f16.f32 "
        "{%0,%1,%2,%3}, {%4,%5,%6,%7}, {%8,%9}, {%0,%1,%2,%3};"
        : "+f"(d[0]), "+f"(d[1]), "+f"(d[2]), "+f"(d[3])
        : "r"(a[0]), "r"(a[1]), "r"(a[2]), "r"(a[3]), "r"(b[0]), "r"(b[1]));
}

// ---------------- kernel 1: x -> fp16 ---------------------------------------
__global__ void convert_x_kernel(const float* __restrict__ x) {
    size_t base = ((size_t)blockIdx.x * blockDim.x + threadIdx.x) * 8;
    if (base >= (size_t)M_TOT * K_TOT) return;
    float v[8];
    *(float4*)(v)     = *(const float4*)(x + base);
    *(float4*)(v + 4) = *(const float4*)(x + base + 4);
    uint4 ph;
    __half* hp = (__half*)&ph;
#pragma unroll
    for (int j = 0; j < 8; j++) hp[j] = __float2half_rn(v[j]);
    *(uint4*)((char*)g_x + base * 2) = ph;
}

// ---------------- kernel 2: W' = W + 4*A@B -> fp16, transposed [N_PAD,K] ----
__global__ void fuse_w_kernel(const float* __restrict__ W,
                              const float* __restrict__ A,
                              const float* __restrict__ Bl) {
    __shared__ __half sh[32][33];
    const int n0 = blockIdx.x * 32, k0 = blockIdx.y * 32;
    const int tx = threadIdx.x & 31, ty = threadIdx.x >> 5;   // 32 x 8
#pragma unroll
    for (int rr = 0; rr < 4; rr++) {
        int k = k0 + ty + rr * 8, n = n0 + tx;
        float acc = W[(size_t)k * N_TOT + n];
#pragma unroll
        for (int r = 0; r < RANK; r++)
            acc += 4.0f * A[k * RANK + r] * Bl[r * N_TOT + n];
        sh[ty + rr * 8][tx] = __float2half_rn(acc);
    }
    __syncthreads();
#pragma unroll
    for (int rr = 0; rr < 4; rr++) {
        int n = n0 + ty + rr * 8, k = k0 + tx;
        g_w[(size_t)n * K_TOT + k] = sh[tx][ty + rr * 8];
    }
}

// ---------------- kernel 3: fp16 mma.sync GEMM ------------------------------
// 8 warps: wm = wid&1 (64-row slab), wn = wid>>1 (32-col slab).
// Warp tile 64x32: mt=4 (m16), nt=4 (n8) -> acc[4][4][4] = 64 regs.
__global__ __launch_bounds__(256, 2)
void gemm_kernel(const float* __restrict__ bias, float* __restrict__ out) {
    extern __shared__ char smem[];
    const uint32_t sb = smem_u32(smem);
    const int tid = threadIdx.x, lane = tid & 31, wid = tid >> 5;
    const int wm = wid & 1;
    const int wn = wid >> 1;
    const int m0 = blockIdx.y * BM;
    const int n0 = blockIdx.x * BN;
    const uint32_t l7 = lane & 7;

    // ---- fragment base addresses (row*128); chunk XOR applied per kk ----
    uint32_t aBase[4];
#pragma unroll
    for (int mt = 0; mt < 4; mt++)
        aBase[mt] = A_OFF + (uint32_t)(wm * 64 + mt * 16 + (lane & 15)) * 128;
    uint32_t bBase[2];
#pragma unroll
    for (int p = 0; p < 2; p++)
        bBase[p] = B_OFF +
            (uint32_t)(wn * 32 + (2 * p + ((lane >> 4) & 1)) * 8 + l7) * 128;
    const uint32_t aSel = lane >> 4;          // A k-half from bit 4
    const uint32_t bSel = (lane >> 3) & 1;    // B k-half from bit 3

    float acc[4][4][4];
#pragma unroll
    for (int i = 0; i < 4; i++)
#pragma unroll
        for (int j = 0; j < 4; j++)
#pragma unroll
            for (int k = 0; k < 4; k++) acc[i][j][k] = 0.0f;

    // ---- stage loader: A 1024 + B 1024 chunks of 16B over 256 threads -----
    auto load_stage = [&](int s, int k0) {
        const uint32_t st = sb + s * STAGE_BYTES;
#pragma unroll
        for (int i = 0; i < 4; i++) {
            int idx = tid + i * 256;
            int row = idx >> 3, ch = idx & 7;
            cp16(st + A_OFF + swz128(row, ch),
                 g_x + (size_t)(m0 + row) * K_TOT + k0 + ch * 8);
        }
#pragma unroll
        for (int i = 0; i < 4; i++) {
            int idx = tid + i * 256;
            int row = idx >> 3, ch = idx & 7;
            cp16(st + B_OFF + swz128(row, ch),
                 g_w + (size_t)(n0 + row) * K_TOT + k0 + ch * 8);
        }
    };

    // xor chunk offsets for fragment loads at k-step kk
    auto xA = [&](int kk) { return 16u * (((uint32_t)(kk * 2) + aSel) ^ l7); };
    auto xB = [&](int kk) { return 16u * (((uint32_t)(kk * 2) + bSel) ^ l7); };

    // ---- prologue: fill 2 stages ----
    load_stage(0, 0);       CP_COMMIT();
    load_stage(1, BK);      CP_COMMIT();
    CP_WAIT1();             // stage 0 complete
    __syncthreads();

    // B fragments double buffer; preload iter0 kk0
    uint32_t bf[2][2][4];
    {
        const uint32_t st0 = sb + 0 * STAGE_BYTES;
#pragma unroll
        for (int p = 0; p < 2; p++) ldm_x4(bf[0][p], st0 + bBase[p] + xB(0));
    }

    // ---- mainloop (3 stages: cur = t%3) ----
    int cur = 0, nxt = 2;
    for (int t = 0; t < KITERS; t++) {
        const uint32_t st = sb + cur * STAGE_BYTES;

        // issue load of stage t+2 (overwrites slot t-1, protected by the
        // barrier at the end of the previous iteration)
        if (t + 2 < KITERS) load_stage(nxt, (t + 2) * BK);
        CP_COMMIT();

#pragma unroll
        for (int kk = 0; kk < 4; kk++) {
            const int cb = kk & 1, nb = cb ^ 1;
            uint32_t a[4][4];
#pragma unroll
            for (int mt = 0; mt < 4; mt++)
                ldm_x4(a[mt], st + aBase[mt] + xA(kk));
            if (kk < 3) {                     // prefetch next kk's B frags
#pragma unroll
                for (int p = 0; p < 2; p++)
                    ldm_x4(bf[nb][p], st + bBase[p] + xB(kk + 1));
            }
#pragma unroll
            for (int mt = 0; mt < 4; mt++)
#pragma unroll
                for (int p = 0; p < 2; p++) {
                    mma_f16(acc[mt][2 * p],     a[mt], &bf[cb][p][0]);
                    mma_f16(acc[mt][2 * p + 1], a[mt], &bf[cb][p][2]);
                }
        }

        CP_WAIT1();                           // stage t+1 landed
        const int nxts = (cur == 2) ? 0 : cur + 1;
        if (t + 1 < KITERS) {
            // cross-iteration prefetch: kk0 B frags of stage t+1 (race-free:
            // next iteration writes stage t+2, not t+1)
            const uint32_t stn = sb + nxts * STAGE_BYTES;
#pragma unroll
            for (int p = 0; p < 2; p++)
                ldm_x4(bf[0][p], stn + bBase[p] + xB(0));
        }
        __syncthreads();                      // all reads of stage t done
        cur = nxts;
        nxt = (nxt == 2) ? 0 : nxt + 1;
    }

    // ---- epilogue: add bias, float2 stores (guard N edge: pad 4800..4863) --
    const int r0 = lane >> 2, c0 = (lane & 3) * 2;
#pragma unroll
    for (int mt = 0; mt < 4; mt++)
#pragma unroll
        for (int nt = 0; nt < 4; nt++) {
            const int col = n0 + wn * 32 + nt * 8 + c0;
            if (col < N_TOT) {
                const float bx = bias[col], by = bias[col + 1];
#pragma unroll
                for (int h = 0; h < 2; h++) {
                    const int row = m0 + wm * 64 + mt * 16 + r0 + h * 8;
                    float2 v;
                    v.x = acc[mt][nt][h * 2 + 0] + bx;
                    v.y = acc[mt][nt][h * 2 + 1] + by;
                    *(float2*)(out + (size_t)row * N_TOT + col) = v;
                }
            }
        }
}

// ---------------------------------------------------------------------------
extern "C" void kernel_launch(void* const* d_in, const int* in_sizes, int n_in,
                              void* d_out, int out_size) {
    const float* x  = (const float*)d_in[0];
    const float* W  = (const float*)d_in[1];
    const float* b  = (const float*)d_in[2];
    const float* lA = (const float*)d_in[3];
    const float* lB = (const float*)d_in[4];
    float* out = (float*)d_out;
    (void)in_sizes; (void)n_in; (void)out_size;

    {   // x -> fp16
        size_t total = (size_t)M_TOT * K_TOT / 8;
        convert_x_kernel<<<(unsigned)((total + 255) / 256), 256>>>(x);
    }
    {   // fuse LoRA + round + transpose W (pad rows 4800..4863 stay zero)
        dim3 grid(N_TOT / 32, K_TOT / 32);   // (150, 50)
        fuse_w_kernel<<<grid, 256>>>(W, lA, lB);
    }
    {   // fp16 tensor-core GEMM
        cudaFuncSetAttribute(gemm_kernel,
                             cudaFuncAttributeMaxDynamicSharedMemorySize,
                             SMEM_TOTAL);
        dim3 grid(N_PAD / BN, M_TOT / BM);   // (38, 64) = 2432 CTAs
        gemm_kernel<<<grid, 256, SMEM_TOTAL>>>(b, out);
    }
}

// round 11
// speedup vs baseline: 1.7619x; 1.0036x over previous
#include <cuda_runtime.h>
#include <cuda_fp16.h>
#include <cstdint>

// LoRAConv1D: out = x @ W + b + 4.0 * (x @ A) @ B
//   x:[8192,1600]f32  W:[1600,4800]f32  b:[4800]  A:[1600,8]  B:[8,4800]
//
// Single-product fp16 tensor path (sm_103 non-'a' target):
//  1) prep kernel (one launch): x -> fp16, and W' = W + 4*A@B -> fp16
//     transposed [N,K] (N padded 4800->4864, pad rows stay zero)
//  2) out = fp16(x)*fp16(W') + b, fp32 accum via mma.sync m16n8k16
//     (calibrated rel err 2.9326e-4 < 1e-3)
//  GEMM (unchanged from the 329us R10 kernel): BM=128 BN=128 BK=64,
//  256 threads (8 warps, 2x4), warp tile 64x32, 3-stage cp.async
//  (32KB/stage) -> 2 CTAs/SM.

#define M_TOT 8192
#define N_TOT 4800
#define N_PAD 4864
#define K_TOT 1600
#define RANK  8

#define BM 128
#define BN 128
#define BK 64
#define KITERS (K_TOT / BK)        // 25

// stage layout (bytes): A[128*128] B[128*128]
#define A_OFF 0
#define B_OFF 16384
#define STAGE_BYTES 32768
#define SMEM_TOTAL (3 * STAGE_BYTES)   // 98304 per CTA -> 2 CTAs/SM

// prep kernel block split
#define CONV_BLOCKS 6400               // 6400*256*8 = 13.1M = M*K
#define FUSE_NB (N_TOT / 32)           // 150
#define FUSE_KB (K_TOT / 64)           // 25
#define FUSE_BLOCKS (FUSE_NB * FUSE_KB)  // 3750

// ---------------- device scratch (static, alloc-free) ----------------------
__device__ __half g_x[(size_t)M_TOT * K_TOT];    // fp16 x
__device__ __half g_w[(size_t)N_PAD * K_TOT];    // [N_PAD,K] fp16 W' (pad=0)

// ---------------- helpers ---------------------------------------------------
__device__ __forceinline__ uint32_t smem_u32(const void* p) {
    uint32_t a;
    asm("{ .reg .u64 t; cvta.to.shared.u64 t, %1; cvt.u32.u64 %0, t; }"
        : "=r"(a) : "l"(p));
    return a;
}
// 128B-pitch SW128 swizzle: 16B chunk ch of row -> ch ^ (row & 7).
__device__ __forceinline__ uint32_t swz128(int row, int ch) {
    return (uint32_t)(row * 128 + 16 * (ch ^ (row & 7)));
}
__device__ __forceinline__ void cp16(uint32_t dst, const void* src) {
    asm volatile("cp.async.cg.shared.global [%0], [%1], 16;"
                 :: "r"(dst), "l"(src));
}
#define CP_COMMIT() asm volatile("cp.async.commit_group;")
#define CP_WAIT1()  asm volatile("cp.async.wait_group 1;")

__device__ __forceinline__ void ldm_x4(uint32_t* r, uint32_t addr) {
    asm volatile("ldmatrix.sync.aligned.m8n8.x4.shared.b16 {%0,%1,%2,%3}, [%4];"
                 : "=r"(r[0]), "=r"(r[1]), "=r"(r[2]), "=r"(r[3]) : "r"(addr));
}
__device__ __forceinline__ void mma_f16(float* d, const uint32_t* a,
                                        const uint32_t* b) {
    asm volatile(
        "mma.sync.aligned.m16n8k16.row.col.f32.f16.f16.f32 "
        "{%0,%1,%2,%3}, {%4,%5,%6,%7}, {%8,%9}, {%0,%1,%2,%3};"
        : "+f"(d[0]), "+f"(d[1]), "+f"(d[2]), "+f"(d[3])
        : "r"(a[0]), "r"(a[1]), "r"(a[2]), "r"(a[3]), "r"(b[0]), "r"(b[1]));
}

// ---------------- kernel 1: merged prep (x convert + W fuse/transpose) ------
// Blocks [0, CONV_BLOCKS): x -> fp16, 8 elements/thread.
// Blocks [CONV_BLOCKS, CONV_BLOCKS+FUSE_BLOCKS): 32n x 64k tile of
//   W' = fp16(W + 4*A@B), transposed to [N,K] with 16B coalesced stores.
__global__ void prep_kernel(const float* __restrict__ x,
                            const float* __restrict__ W,
                            const float* __restrict__ A,
                            const float* __restrict__ Bl) {
    const int tid = threadIdx.x;
    if (blockIdx.x < CONV_BLOCKS) {
        size_t base = ((size_t)blockIdx.x * 256 + tid) * 8;
        float v[8];
        *(float4*)(v)     = *(const float4*)(x + base);
        *(float4*)(v + 4) = *(const float4*)(x + base + 4);
        uint4 ph;
        __half* hp = (__half*)&ph;
#pragma unroll
        for (int j = 0; j < 8; j++) hp[j] = __float2half_rn(v[j]);
        *(uint4*)((char*)g_x + base * 2) = ph;
        return;
    }

    // ---- fuse part ----
    __shared__ uint32_t sh[32][37];      // [n_local][k_word], stride 37: no conflicts
    const int bid = blockIdx.x - CONV_BLOCKS;
    const int nb = bid % FUSE_NB, kb = bid / FUSE_NB;
    const int n0 = nb * 32, k0 = kb * 64;
    const int tx = tid & 31, ty = tid >> 5;      // 32 x 8

    // thread computes 8 consecutive k (= 4 k-words) for one n
#pragma unroll
    for (int w2 = 0; w2 < 4; w2++) {
        __half pair[2];
#pragma unroll
        for (int e = 0; e < 2; e++) {
            const int k = k0 + ty * 8 + w2 * 2 + e;
            const int n = n0 + tx;
            float acc = W[(size_t)k * N_TOT + n];
#pragma unroll
            for (int r = 0; r < RANK; r++)
                acc += 4.0f * A[k * RANK + r] * Bl[r * N_TOT + n];
            pair[e] = __float2half_rn(acc);
        }
        sh[tx][ty * 4 + w2] = *(const uint32_t*)pair;
    }
    __syncthreads();

    // store: thread -> one uint4 (8 halves) of output row n_local
    {
        const int n_local = tid >> 3;            // 0..31
        const int jw = (tid & 7) * 4;            // word index 0,4,...,28
        uint4 v;
        v.x = sh[n_local][jw + 0];
        v.y = sh[n_local][jw + 1];
        v.z = sh[n_local][jw + 2];
        v.w = sh[n_local][jw + 3];
        *(uint4*)(g_w + (size_t)(n0 + n_local) * K_TOT + k0 + (tid & 7) * 8) = v;
    }
}

// ---------------- kernel 2: fp16 mma.sync GEMM (unchanged from R10) ---------
// 8 warps: wm = wid&1 (64-row slab), wn = wid>>1 (32-col slab).
// Warp tile 64x32: mt=4 (m16), nt=4 (n8) -> acc[4][4][4] = 64 regs.
__global__ __launch_bounds__(256, 2)
void gemm_kernel(const float* __restrict__ bias, float* __restrict__ out) {
    extern __shared__ char smem[];
    const uint32_t sb = smem_u32(smem);
    const int tid = threadIdx.x, lane = tid & 31, wid = tid >> 5;
    const int wm = wid & 1;
    const int wn = wid >> 1;
    const int m0 = blockIdx.y * BM;
    const int n0 = blockIdx.x * BN;
    const uint32_t l7 = lane & 7;

    uint32_t aBase[4];
#pragma unroll
    for (int mt = 0; mt < 4; mt++)
        aBase[mt] = A_OFF + (uint32_t)(wm * 64 + mt * 16 + (lane & 15)) * 128;
    uint32_t bBase[2];
#pragma unroll
    for (int p = 0; p < 2; p++)
        bBase[p] = B_OFF +
            (uint32_t)(wn * 32 + (2 * p + ((lane >> 4) & 1)) * 8 + l7) * 128;
    const uint32_t aSel = lane >> 4;
    const uint32_t bSel = (lane >> 3) & 1;

    float acc[4][4][4];
#pragma unroll
    for (int i = 0; i < 4; i++)
#pragma unroll
        for (int j = 0; j < 4; j++)
#pragma unroll
            for (int k = 0; k < 4; k++) acc[i][j][k] = 0.0f;

    auto load_stage = [&](int s, int k0) {
        const uint32_t st = sb + s * STAGE_BYTES;
#pragma unroll
        for (int i = 0; i < 4; i++) {
            int idx = tid + i * 256;
            int row = idx >> 3, ch = idx & 7;
            cp16(st + A_OFF + swz128(row, ch),
                 g_x + (size_t)(m0 + row) * K_TOT + k0 + ch * 8);
        }
#pragma unroll
        for (int i = 0; i < 4; i++) {
            int idx = tid + i * 256;
            int row = idx >> 3, ch = idx & 7;
            cp16(st + B_OFF + swz128(row, ch),
                 g_w + (size_t)(n0 + row) * K_TOT + k0 + ch * 8);
        }
    };

    auto xA = [&](int kk) { return 16u * (((uint32_t)(kk * 2) + aSel) ^ l7); };
    auto xB = [&](int kk) { return 16u * (((uint32_t)(kk * 2) + bSel) ^ l7); };

    load_stage(0, 0);       CP_COMMIT();
    load_stage(1, BK);      CP_COMMIT();
    CP_WAIT1();
    __syncthreads();

    uint32_t bf[2][2][4];
    {
        const uint32_t st0 = sb + 0 * STAGE_BYTES;
#pragma unroll
        for (int p = 0; p < 2; p++) ldm_x4(bf[0][p], st0 + bBase[p] + xB(0));
    }

    int cur = 0, nxt = 2;
    for (int t = 0; t < KITERS; t++) {
        const uint32_t st = sb + cur * STAGE_BYTES;

        if (t + 2 < KITERS) load_stage(nxt, (t + 2) * BK);
        CP_COMMIT();

#pragma unroll
        for (int kk = 0; kk < 4; kk++) {
            const int cb = kk & 1, nb2 = cb ^ 1;
            uint32_t a[4][4];
#pragma unroll
            for (int mt = 0; mt < 4; mt++)
                ldm_x4(a[mt], st + aBase[mt] + xA(kk));
            if (kk < 3) {
#pragma unroll
                for (int p = 0; p < 2; p++)
                    ldm_x4(bf[nb2][p], st + bBase[p] + xB(kk + 1));
            }
#pragma unroll
            for (int mt = 0; mt < 4; mt++)
#pragma unroll
                for (int p = 0; p < 2; p++) {
                    mma_f16(acc[mt][2 * p],     a[mt], &bf[cb][p][0]);
                    mma_f16(acc[mt][2 * p + 1], a[mt], &bf[cb][p][2]);
                }
        }

        CP_WAIT1();
        const int nxts = (cur == 2) ? 0 : cur + 1;
        if (t + 1 < KITERS) {
            const uint32_t stn = sb + nxts * STAGE_BYTES;
#pragma unroll
            for (int p = 0; p < 2; p++)
                ldm_x4(bf[0][p], stn + bBase[p] + xB(0));
        }
        __syncthreads();
        cur = nxts;
        nxt = (nxt == 2) ? 0 : nxt + 1;
    }

    const int r0 = lane >> 2, c0 = (lane & 3) * 2;
#pragma unroll
    for (int mt = 0; mt < 4; mt++)
#pragma unroll
        for (int nt = 0; nt < 4; nt++) {
            const int col = n0 + wn * 32 + nt * 8 + c0;
            if (col < N_TOT) {
                const float bx = bias[col], by = bias[col + 1];
#pragma unroll
                for (int h = 0; h < 2; h++) {
                    const int row = m0 + wm * 64 + mt * 16 + r0 + h * 8;
                    float2 v;
                    v.x = acc[mt][nt][h * 2 + 0] + bx;
                    v.y = acc[mt][nt][h * 2 + 1] + by;
                    *(float2*)(out + (size_t)row * N_TOT + col) = v;
                }
            }
        }
}

// ---------------------------------------------------------------------------
extern "C" void kernel_launch(void* const* d_in, const int* in_sizes, int n_in,
                              void* d_out, int out_size) {
    const float* x  = (const float*)d_in[0];
    const float* W  = (const float*)d_in[1];
    const float* b  = (const float*)d_in[2];
    const float* lA = (const float*)d_in[3];
    const float* lB = (const float*)d_in[4];
    float* out = (float*)d_out;
    (void)in_sizes; (void)n_in; (void)out_size;

    // one merged prep launch: x->fp16 convert + LoRA-fused W transpose
    prep_kernel<<<CONV_BLOCKS + FUSE_BLOCKS, 256>>>(x, W, lA, lB);

    // fp16 tensor-core GEMM
    cudaFuncSetAttribute(gemm_kernel,
                         cudaFuncAttributeMaxDynamicSharedMemorySize,
                         SMEM_TOTAL);
    dim3 grid(N_PAD / BN, M_TOT / BM);   // (38, 64) = 2432 CTAs
    gemm_kernel<<<grid, 256, SMEM_TOTAL>>>(b, out);
}